// round 13
// baseline (speedup 1.0000x reference)
#include <cuda_runtime.h>
#include <cuda_bf16.h>
#include <math.h>
#include <stdint.h>

// ---------------------------------------------------------------------------
// Problem constants
// ---------------------------------------------------------------------------
#define BATCH 16
#define SEQL  128
#define IN_DIM 1218
#define HID 200          // H
#define G4  800          // 4*H
#define LSTMD 400
#define SMAX 8001        // (L-1)(L-2)/2
#define ML (BATCH*SEQL)  // 2048
#define OUT_BASE (BATCH*SMAX*LSTMD)  // 51,206,400

// ---------------------------------------------------------------------------
// Scratch (static device globals -- no runtime allocation).
// Referenced ONLY inside device code (host-shadow-address pitfall).
// ---------------------------------------------------------------------------
__device__ float g_emb[ML * IN_DIM];        // (b*L+t, 1218)
__device__ float g_gx [2 * ML * G4];        // [dir][b][t][800]  (reused both layers)
__device__ float g_h0 [ML * LSTMD];         // layer0 output [b][t][400]
__device__ float g_h1 [ML * LSTMD];         // layer1 output
__device__ float g_hx [2 * 32 * 208];       // h exchange [parity][pair][<=208]
__device__ int   g_bar[32 * 64];            // step counters, one per 256B line
__device__ int   g_lens[BATCH];
__device__ int   g_ij  [BATCH * SMAX];

// ---------------------------------------------------------------------------
// lens[b] = #(word_idxs != PAD).  Block 0 also zeroes the (padded) counters.
// ---------------------------------------------------------------------------
__global__ void lens_kernel(const int* __restrict__ wi)
{
    int b = blockIdx.x, t = threadIdx.x;
    if (b == 0 && t < 32) g_bar[t * 64] = 0;
    int v = (wi[b * SEQL + t] != 0) ? 1 : 0;
    int cnt = __syncthreads_count(v);
    if (t == 0) g_lens[b] = cnt;
}

// ---------------------------------------------------------------------------
// Embedding concat: bert part (dims 450..1217)
// ---------------------------------------------------------------------------
__global__ void embed_bert_kernel(const float* __restrict__ bert)
{
    long idx = (long)blockIdx.x * blockDim.x + threadIdx.x;  // ML*768
    if (idx >= (long)ML * 768) return;
    int d  = (int)(idx % 768);
    int bt = (int)(idx / 768);
    g_emb[(size_t)bt * IN_DIM + 450 + d] = bert[idx];
}

// ---------------------------------------------------------------------------
// Embedding concat: word + pos/dep/ent/iob (dims 0..449)
// ---------------------------------------------------------------------------
__global__ void embed_wordmisc_kernel(const float* __restrict__ ext_emb,
                                      const float* __restrict__ word_emb,
                                      const float* __restrict__ pos_emb,
                                      const float* __restrict__ dep_emb,
                                      const float* __restrict__ ent_emb,
                                      const float* __restrict__ iob_emb,
                                      const int* __restrict__ word_idxs,
                                      const int* __restrict__ pos_idxs,
                                      const int* __restrict__ dep_idxs,
                                      const int* __restrict__ ent_idxs,
                                      const int* __restrict__ iob_idxs)
{
    long idx = (long)blockIdx.x * blockDim.x + threadIdx.x;  // ML*450
    if (idx >= (long)ML * 450) return;
    int d  = (int)(idx % 450);
    int bt = (int)(idx / 450);
    float v;
    if (d < 300) {
        int wi  = word_idxs[bt];
        int wid = (wi >= 20000) ? 1 : wi;
        v = ext_emb[(size_t)wi * 300 + d] + word_emb[(size_t)wid * 300 + d];
    } else if (d < 350) {
        v = pos_emb[pos_idxs[bt] * 50 + (d - 300)];
    } else if (d < 400) {
        v = dep_emb[dep_idxs[bt] * 50 + (d - 350)];
    } else if (d < 425) {
        v = ent_emb[ent_idxs[bt] * 25 + (d - 400)];
    } else {
        v = iob_emb[iob_idxs[bt] * 25 + (d - 425)];
    }
    g_emb[(size_t)bt * IN_DIM + d] = v;
}

// ---------------------------------------------------------------------------
// tf32 tensor-core GEMM, BN=128 (warp tile 32x64, 8 n-tiles).
// EXACT round-11 configuration (proven 867.4us build): __launch_bounds__(256),
// no min-blocks clause.
// ---------------------------------------------------------------------------
#define BM 128
#define BN 128
#define BK 16
#define ASTR 136
#define BSTR 136

__device__ __forceinline__ uint32_t f2tf32(float v)
{
    uint32_t r;
    asm("cvt.rna.tf32.f32 %0, %1;" : "=r"(r) : "f"(v));
    return r;
}

__global__ void __launch_bounds__(256)
gemm_tf32_kernel(const float* __restrict__ Wall,
                 const float* __restrict__ bih_all, const float* __restrict__ bhh_all,
                 int M, int N, int K, int src_sel)
{
    const float* A = src_sel ? g_h0 : g_emb;
    const int dir = blockIdx.z;
    const float* W  = Wall + (size_t)dir * N * K;
    const float* bi = bih_all + dir * N;
    const float* bh = bhh_all + dir * N;
    float* C = g_gx + (size_t)dir * M * N;

    __shared__ uint32_t As[2][BK][ASTR];
    __shared__ uint32_t Bs[2][BK][BSTR];

    const int tid  = threadIdx.x;
    const int m0   = blockIdx.y * BM;
    const int n0   = blockIdx.x * BN;
    const int warp = tid >> 5;
    const int lane = tid & 31;
    const int wm   = warp & 3;       // 0..3 -> m
    const int wn   = warp >> 2;      // 0..1 -> n (64 each)
    const int gid  = lane >> 2;      // 0..7
    const int tig  = lane & 3;       // 0..3

    const int arow = tid >> 2;          // 0..63
    const int akq  = (tid & 3) * 4;     // 0,4,8,12

    float acc[2][8][4];
#pragma unroll
    for (int mi = 0; mi < 2; mi++)
#pragma unroll
        for (int ni = 0; ni < 8; ni++)
#pragma unroll
            for (int r = 0; r < 4; r++) acc[mi][ni][r] = 0.f;

    const int numk = (K + BK - 1) / BK;
    float aR[8], bR[8];

    // prefetch stage 0
    {
        const int k0 = 0;
#pragma unroll
        for (int u = 0; u < 2; u++) {
            int m = m0 + arow + u * 64;
            const float* ap = A + (size_t)m * K + k0 + akq;
            int n = n0 + arow + u * 64;
            const float* wp = W + (size_t)n * K + k0 + akq;
#pragma unroll
            for (int c = 0; c < 4; c++) {
                int kk = k0 + akq + c;
                aR[u * 4 + c] = (kk < K) ? ap[c] : 0.f;
                bR[u * 4 + c] = (n < N && kk < K) ? wp[c] : 0.f;
            }
        }
    }

    for (int s = 0; s < numk; s++) {
        const int buf = s & 1;
#pragma unroll
        for (int u = 0; u < 2; u++)
#pragma unroll
            for (int c = 0; c < 4; c++) {
                As[buf][akq + c][arow + u * 64] = f2tf32(aR[u * 4 + c]);
                Bs[buf][akq + c][arow + u * 64] = f2tf32(bR[u * 4 + c]);
            }
        __syncthreads();

        if (s + 1 < numk) {
            const int k0 = (s + 1) * BK;
#pragma unroll
            for (int u = 0; u < 2; u++) {
                int m = m0 + arow + u * 64;
                const float* ap = A + (size_t)m * K + k0 + akq;
                int n = n0 + arow + u * 64;
                const float* wp = W + (size_t)n * K + k0 + akq;
#pragma unroll
                for (int c = 0; c < 4; c++) {
                    int kk = k0 + akq + c;
                    aR[u * 4 + c] = (kk < K) ? ap[c] : 0.f;
                    bR[u * 4 + c] = (n < N && kk < K) ? wp[c] : 0.f;
                }
            }
        }

#pragma unroll
        for (int kk = 0; kk < 2; kk++) {
            const int kb = kk * 8;
            uint32_t af[2][4];
#pragma unroll
            for (int mi = 0; mi < 2; mi++) {
                int m = wm * 32 + mi * 16 + gid;
                af[mi][0] = As[buf][kb + tig][m];
                af[mi][1] = As[buf][kb + tig][m + 8];
                af[mi][2] = As[buf][kb + tig + 4][m];
                af[mi][3] = As[buf][kb + tig + 4][m + 8];
            }
#pragma unroll
            for (int ni = 0; ni < 8; ni++) {
                int n = wn * 64 + ni * 8 + gid;
                uint32_t b0 = Bs[buf][kb + tig][n];
                uint32_t b1 = Bs[buf][kb + tig + 4][n];
#pragma unroll
                for (int mi = 0; mi < 2; mi++) {
                    asm volatile(
                        "mma.sync.aligned.m16n8k8.row.col.f32.tf32.tf32.f32 "
                        "{%0,%1,%2,%3},{%4,%5,%6,%7},{%8,%9},{%0,%1,%2,%3};"
                        : "+f"(acc[mi][ni][0]), "+f"(acc[mi][ni][1]),
                          "+f"(acc[mi][ni][2]), "+f"(acc[mi][ni][3])
                        : "r"(af[mi][0]), "r"(af[mi][1]),
                          "r"(af[mi][2]), "r"(af[mi][3]),
                          "r"(b0), "r"(b1));
                }
            }
        }
        __syncthreads();
    }

#pragma unroll
    for (int mi = 0; mi < 2; mi++) {
#pragma unroll
        for (int ni = 0; ni < 8; ni++) {
            int m = m0 + wm * 32 + mi * 16 + gid;
            int n = n0 + wn * 64 + ni * 8 + tig * 2;
            if (n < N) {
                float bs0 = bi[n] + bh[n];
                float bs1 = bi[n + 1] + bh[n + 1];
                float2 v0 = make_float2(acc[mi][ni][0] + bs0, acc[mi][ni][1] + bs1);
                float2 v1 = make_float2(acc[mi][ni][2] + bs0, acc[mi][ni][3] + bs1);
                *(float2*)&C[(size_t)m * N + n] = v0;
                *(float2*)&C[(size_t)(m + 8) * N + n] = v1;
            }
        }
    }
}

// ---------------------------------------------------------------------------
// Recurrence, quad-gate layout.  FROZEN from round 10 (proven 310 us).
// ---------------------------------------------------------------------------
__device__ __forceinline__ void fence_acqrel_gpu()
{
    asm volatile("fence.acq_rel.gpu;" ::: "memory");
}
__device__ __forceinline__ void red_relaxed_add(int* p)
{
    asm volatile("red.relaxed.gpu.global.add.u32 [%0], 1;" :: "l"(p) : "memory");
}
__device__ __forceinline__ int ld_relaxed(const int* p)
{
    int v;
    asm volatile("ld.relaxed.gpu.global.u32 %0, [%1];" : "=r"(v) : "l"(p) : "memory");
    return v;
}
__device__ __forceinline__ float fast_sigmoid(float x)
{
    return __fdividef(1.f, 1.f + __expf(-x));
}
__device__ __forceinline__ float fast_tanh(float x)
{
    float e = __expf(-2.f * x);
    return (1.f - e) * __fdividef(1.f, 1.f + e);
}

__global__ void __launch_bounds__(224, 1)
recur_kernel(const float* __restrict__ Whh,   // [2][800][200]
             int layer_sel)
{
    const int r    = (int)(blockIdx.x & 3);   // rank in group 0..3
    const int pair = (int)(blockIdx.x >> 2);  // 0..31
    const int dir  = pair >> 4;
    const int b    = pair & 15;
    const int tid  = threadIdx.x;
    const int len  = g_lens[b];
    const int tbase = layer_sel ? 512 : 0;
    int* cnt = &g_bar[pair * 64];
    float* outh = layer_sel ? g_h1 : g_h0;

    __shared__ float4 hs4[50];
    float* hs = (float*)hs4;

    const int q       = tid & 3;
    const int u_local = tid >> 2;
    const int gu      = r * 50 + u_local;
    const int grow    = q * 200 + gu;
    const unsigned shmask = (tid < 192) ? 0xFFFFFFFFu : 0xFFu;
    const int lbase = (tid & 31) & ~3;

    float4 W4[50];
    if (tid < 200) {
        const float4* wp = (const float4*)(Whh + ((size_t)dir * G4 + grow) * HID);
#pragma unroll
        for (int kk = 0; kk < 50; kk++) W4[kk] = wp[kk];
    }
    if (tid < 50) hs4[tid] = make_float4(0.f, 0.f, 0.f, 0.f);

    float c = 0.f;
    const long gstep = dir ? -(long)G4 : (long)G4;
    const int  tpf   = dir ? (SEQL - 1) : 0;
    const float* gp  = g_gx + ((size_t)dir * BATCH + b) * SEQL * G4
                            + (size_t)tpf * G4 + grow;
    float gcur = 0.f;
    if (tid < 200) gcur = __ldcg(gp);
    __syncthreads();

    for (int t = 0; t < SEQL; t++) {
        const int tp  = dir ? (SEQL - 1 - t) : t;
        const int par = t & 1;
        const float mt = (tp < len) ? 1.f : 0.f;

        if (tid < 200) {
            float a0 = 0.f, a1 = 0.f, a2 = 0.f, a3 = 0.f;
#pragma unroll
            for (int kk = 0; kk < 50; kk++) {
                float4 hv = hs4[kk];
                a0 += W4[kk].x * hv.x;
                a1 += W4[kk].y * hv.y;
                a2 += W4[kk].z * hv.z;
                a3 += W4[kk].w * hv.w;
            }
            float s = (a0 + a1) + (a2 + a3) + gcur;
            gp += gstep;
            if (t + 1 < SEQL) gcur = __ldcg(gp);

            float v = (q == 2) ? fast_tanh(s) : fast_sigmoid(s);
            float ii = __shfl_sync(shmask, v, lbase + 0);
            float ff = __shfl_sync(shmask, v, lbase + 1);
            float gg = __shfl_sync(shmask, v, lbase + 2);
            float oo = __shfl_sync(shmask, v, lbase + 3);

            float cn = ff * c + ii * gg;
            float hn = oo * fast_tanh(cn);
            float hp = hs[gu];
            float hnew = mt * hn + (1.f - mt) * hp;
            c = mt * cn + (1.f - mt) * c;

            if (q == 0) {
                outh[((size_t)b * SEQL + tp) * LSTMD + dir * HID + gu] = mt * hn;
                __stcg(g_hx + ((size_t)par * 32 + pair) * 208 + gu, hnew);
            }
        }
        __syncthreads();

        if (tid == 0) {
            fence_acqrel_gpu();
            red_relaxed_add(cnt);
            const int target = tbase + 4 * (t + 1);
            while (ld_relaxed(cnt) < target) { }
            fence_acqrel_gpu();
        }
        __syncthreads();

        if (tid < 200)
            hs[tid] = __ldcg(g_hx + ((size_t)par * 32 + pair) * 208 + tid);
        __syncthreads();
    }
}

// ---------------------------------------------------------------------------
// s -> (i,j) table + lens-2 tail
// ---------------------------------------------------------------------------
__global__ void ij_kernel(float* __restrict__ out, int extra)
{
    int idx = blockIdx.x * blockDim.x + threadIdx.x;
    if (idx < extra && idx < BATCH)
        out[(size_t)OUT_BASE + idx] = (float)(g_lens[idx] - 2);
    if (idx >= BATCH * SMAX) return;
    int s = idx % SMAX;
    int b = idx / SMAX;
    int n = g_lens[b] - 1;
    int cnt = n * (n - 1) / 2;
    int val = 0;
    if (s < cnt) {
        float fn = (float)(2 * n - 1);
        int i = (int)floorf((fn - sqrtf(fn * fn - 8.0f * (float)s)) * 0.5f);
        if (i < 0) i = 0;
        if (i > n - 2) i = n - 2;
        while ((i + 1) * (2 * n - 2 - i) / 2 <= s) i++;
        while (i > 0 && i * (2 * n - 1 - i) / 2 > s) i--;
        int j = i + 1 + (s - i * (2 * n - 1 - i) / 2);
        val = (i << 8) | j;
    }
    g_ij[idx] = val;
}

// ---------------------------------------------------------------------------
// Span emit (float4 granularity)
// ---------------------------------------------------------------------------
__global__ void span_kernel(float* __restrict__ out)
{
    long idx = (long)blockIdx.x * blockDim.x + threadIdx.x; // over 16*8001*100
    if (idx >= (long)BATCH * SMAX * 100) return;
    int d4 = (int)(idx % 100);
    int bs = (int)(idx / 100);
    int s = bs % SMAX;
    int b = bs / SMAX;
    int n = g_lens[b] - 1;
    int cnt = n * (n - 1) / 2;
    float4 v = make_float4(0.f, 0.f, 0.f, 0.f);
    if (s < cnt) {
        int p = g_ij[bs];
        int i = p >> 8;
        int j = p & 255;
        const float4* hb = (const float4*)(g_h1 + (size_t)b * SEQL * LSTMD);
        float4 x, y;
        if (d4 < 50) {
            x = hb[j * 100 + d4];
            y = hb[i * 100 + d4];
        } else {
            x = hb[(i + 1) * 100 + d4];
            y = hb[(j + 1) * 100 + d4];
        }
        v.x = x.x - y.x; v.y = x.y - y.y; v.z = x.z - y.z; v.w = x.w - y.w;
    }
    ((float4*)out)[idx] = v;
}

// ---------------------------------------------------------------------------
// Launch.  ncu captures launch index 3 -> gemm0 goes there.
//   0 lens, 1 embed_bert, 2 embed_wordmisc, 3 gemm0, 4 recur0,
//   5 gemm1, 6 recur1, 7 ij, 8 span
// ---------------------------------------------------------------------------
extern "C" void kernel_launch(void* const* d_in, const int* in_sizes, int n_in,
                              void* d_out, int out_size)
{
    const float* ext_emb  = (const float*)d_in[0];
    const float* word_emb = (const float*)d_in[1];
    const float* pos_emb  = (const float*)d_in[2];
    const float* dep_emb  = (const float*)d_in[3];
    const float* ent_emb  = (const float*)d_in[4];
    const float* iob_emb  = (const float*)d_in[5];
    const float* w_ih_l0  = (const float*)d_in[6];
    const float* w_hh_l0  = (const float*)d_in[7];
    const float* b_ih_l0  = (const float*)d_in[8];
    const float* b_hh_l0  = (const float*)d_in[9];
    const float* w_ih_l1  = (const float*)d_in[10];
    const float* w_hh_l1  = (const float*)d_in[11];
    const float* b_ih_l1  = (const float*)d_in[12];
    const float* b_hh_l1  = (const float*)d_in[13];
    const float* bert     = (const float*)d_in[14];
    const int* word_idxs  = (const int*)d_in[15];
    const int* pos_idxs   = (const int*)d_in[16];
    const int* dep_idxs   = (const int*)d_in[17];
    const int* ent_idxs   = (const int*)d_in[18];
    const int* iob_idxs   = (const int*)d_in[19];
    float* out = (float*)d_out;

    // 0. lengths + padded counter reset
    lens_kernel<<<BATCH, SEQL>>>(word_idxs);

    // 1. embed: bert slice
    {
        long tb = (long)ML * 768;
        embed_bert_kernel<<<(int)((tb + 255) / 256), 256>>>(bert);
    }

    // 2. embed: word + misc slices
    {
        long tw = (long)ML * 450;
        embed_wordmisc_kernel<<<(int)((tw + 255) / 256), 256>>>(
            ext_emb, word_emb, pos_emb, dep_emb, ent_emb, iob_emb,
            word_idxs, pos_idxs, dep_idxs, ent_idxs, iob_idxs);
    }

    // 3. layer0 input projection  (M=2048, N=800, K=1218), A = g_emb
    {
        dim3 grid((G4 + BN - 1) / BN, ML / BM, 2);
        gemm_tf32_kernel<<<grid, 256>>>(w_ih_l0, b_ih_l0, b_hh_l0,
                                        ML, G4, IN_DIM, 0);
    }

    // 4. layer0 recurrence (128 CTAs, 32 groups x 4)
    recur_kernel<<<128, 224>>>(w_hh_l0, 0);

    // 5. layer1 input projection (M=2048, N=800, K=400), A = g_h0
    {
        dim3 grid((G4 + BN - 1) / BN, ML / BM, 2);
        gemm_tf32_kernel<<<grid, 256>>>(w_ih_l1, b_ih_l1, b_hh_l1,
                                        ML, G4, LSTMD, 1);
    }

    // 6. layer1 recurrence
    recur_kernel<<<128, 224>>>(w_hh_l1, 1);

    // 7. s -> (i,j) table (+ lens-2 tail if present)
    {
        int extra = out_size - OUT_BASE;
        if (extra < 0) extra = 0;
        int tot = BATCH * SMAX;
        ij_kernel<<<(tot + 255) / 256, 256>>>(out, extra);
    }

    // 8. span emit
    {
        long tot = (long)BATCH * SMAX * 100;
        int blocks = (int)((tot + 255) / 256);
        span_kernel<<<blocks, 256>>>(out);
    }
}

// round 16
// speedup vs baseline: 1.0193x; 1.0193x over previous
#include <cuda_runtime.h>
#include <cuda_bf16.h>
#include <math.h>
#include <stdint.h>

// ---------------------------------------------------------------------------
// Problem constants
// ---------------------------------------------------------------------------
#define BATCH 16
#define SEQL  128
#define IN_DIM 1218
#define HID 200          // H
#define G4  800          // 4*H
#define LSTMD 400
#define SMAX 8001        // (L-1)(L-2)/2
#define ML (BATCH*SEQL)  // 2048
#define OUT_BASE (BATCH*SMAX*LSTMD)  // 51,206,400

// ---------------------------------------------------------------------------
// Scratch (static device globals -- no runtime allocation).
// Referenced ONLY inside device code (host-shadow-address pitfall).
// ---------------------------------------------------------------------------
__device__ float g_emb[ML * IN_DIM];        // (b*L+t, 1218)
__device__ float g_gx [2 * ML * G4];        // [dir][b][t][800]  (reused both layers)
__device__ float g_h0 [ML * LSTMD];         // layer0 output [b][t][400]
__device__ float g_h1 [ML * LSTMD];         // layer1 output
__device__ float g_hx [2 * 32 * 208];       // h exchange [parity][pair][<=208]
__device__ int   g_bar[32 * 64];            // step counters, one per 256B line
__device__ int   g_lens[BATCH];
__device__ int   g_ij  [BATCH * SMAX];

// ---------------------------------------------------------------------------
// lens[b] = #(word_idxs != PAD).  Block 0 also zeroes the (padded) counters.
// ---------------------------------------------------------------------------
__global__ void lens_kernel(const int* __restrict__ wi)
{
    int b = blockIdx.x, t = threadIdx.x;
    if (b == 0 && t < 32) g_bar[t * 64] = 0;
    int v = (wi[b * SEQL + t] != 0) ? 1 : 0;
    int cnt = __syncthreads_count(v);
    if (t == 0) g_lens[b] = cnt;
}

// ---------------------------------------------------------------------------
// Embedding concat: bert part (dims 450..1217)
// ---------------------------------------------------------------------------
__global__ void embed_bert_kernel(const float* __restrict__ bert)
{
    long idx = (long)blockIdx.x * blockDim.x + threadIdx.x;  // ML*768
    if (idx >= (long)ML * 768) return;
    int d  = (int)(idx % 768);
    int bt = (int)(idx / 768);
    g_emb[(size_t)bt * IN_DIM + 450 + d] = bert[idx];
}

// ---------------------------------------------------------------------------
// Embedding concat: word + pos/dep/ent/iob (dims 0..449)
// ---------------------------------------------------------------------------
__global__ void embed_wordmisc_kernel(const float* __restrict__ ext_emb,
                                      const float* __restrict__ word_emb,
                                      const float* __restrict__ pos_emb,
                                      const float* __restrict__ dep_emb,
                                      const float* __restrict__ ent_emb,
                                      const float* __restrict__ iob_emb,
                                      const int* __restrict__ word_idxs,
                                      const int* __restrict__ pos_idxs,
                                      const int* __restrict__ dep_idxs,
                                      const int* __restrict__ ent_idxs,
                                      const int* __restrict__ iob_idxs)
{
    long idx = (long)blockIdx.x * blockDim.x + threadIdx.x;  // ML*450
    if (idx >= (long)ML * 450) return;
    int d  = (int)(idx % 450);
    int bt = (int)(idx / 450);
    float v;
    if (d < 300) {
        int wi  = word_idxs[bt];
        int wid = (wi >= 20000) ? 1 : wi;
        v = ext_emb[(size_t)wi * 300 + d] + word_emb[(size_t)wid * 300 + d];
    } else if (d < 350) {
        v = pos_emb[pos_idxs[bt] * 50 + (d - 300)];
    } else if (d < 400) {
        v = dep_emb[dep_idxs[bt] * 50 + (d - 350)];
    } else if (d < 425) {
        v = ent_emb[ent_idxs[bt] * 25 + (d - 400)];
    } else {
        v = iob_emb[iob_idxs[bt] * 25 + (d - 425)];
    }
    g_emb[(size_t)bt * IN_DIM + d] = v;
}

// ---------------------------------------------------------------------------
// tf32 tensor-core GEMM, BN=128, uint2-paired smem fragments:
//  As2[buf][kk][t][m] = (tf32 A[m][kk*8+t], tf32 A[m][kk*8+t+4])
//  A-frag = 2x LDS.64, B-frag = 1x LDS.64 (halved LDS count vs scalar).
//  Single __syncthreads per BK stage (compute buf[s], then STS buf[s+1]).
// MMA sequence and accumulation order unchanged from the proven kernel.
// No lambdas (manually inlined).  No min-blocks clause.
// ---------------------------------------------------------------------------
#define BM 128
#define BN 128
#define BK 16
#define MSTR 132

__device__ __forceinline__ uint32_t f2tf32(float v)
{
    uint32_t r;
    asm("cvt.rna.tf32.f32 %0, %1;" : "=r"(r) : "f"(v));
    return r;
}

__global__ void __launch_bounds__(256)
gemm_tf32_kernel(const float* __restrict__ Wall,
                 const float* __restrict__ bih_all, const float* __restrict__ bhh_all,
                 int M, int N, int K, int src_sel)
{
    const float* A = src_sel ? g_h0 : g_emb;
    const int dir = blockIdx.z;
    const float* W  = Wall + (size_t)dir * N * K;
    const float* bi = bih_all + dir * N;
    const float* bh = bhh_all + dir * N;
    float* C = g_gx + (size_t)dir * M * N;

    __shared__ uint2 As2[2][2][4][MSTR];
    __shared__ uint2 Bs2[2][2][4][MSTR];

    const int tid  = threadIdx.x;
    const int m0   = blockIdx.y * BM;
    const int n0   = blockIdx.x * BN;
    const int warp = tid >> 5;
    const int lane = tid & 31;
    const int wm   = warp & 3;       // 0..3 -> m
    const int wn   = warp >> 2;      // 0..1 -> n (64 each)
    const int gid  = lane >> 2;      // 0..7
    const int tig  = lane & 3;       // 0..3

    const int arow  = tid >> 2;         // 0..63
    const int akq   = (tid & 3) * 4;    // 0,4,8,12
    const int kkA   = akq >> 3;         // 0 or 1
    const int halfA = (akq >> 2) & 1;   // 0 -> .x, 1 -> .y

    float acc[2][8][4];
#pragma unroll
    for (int mi = 0; mi < 2; mi++)
#pragma unroll
        for (int ni = 0; ni < 8; ni++)
#pragma unroll
            for (int r = 0; r < 4; r++) acc[mi][ni][r] = 0.f;

    const int numk = (K + BK - 1) / BK;
    float aR[8], bR[8];

    // ---- prolog: load + store stage 0 into buf 0 ----
    {
        const int k0 = 0;
#pragma unroll
        for (int u = 0; u < 2; u++) {
            int m = m0 + arow + u * 64;
            const float* ap = A + (size_t)m * K + k0 + akq;
            int n = n0 + arow + u * 64;
            const float* wp = W + (size_t)n * K + k0 + akq;
#pragma unroll
            for (int c = 0; c < 4; c++) {
                int kk = k0 + akq + c;
                aR[u * 4 + c] = (kk < K) ? ap[c] : 0.f;
                bR[u * 4 + c] = (n < N && kk < K) ? wp[c] : 0.f;
            }
        }
#pragma unroll
        for (int u = 0; u < 2; u++)
#pragma unroll
            for (int c = 0; c < 4; c++) {
                uint32_t* pa = (uint32_t*)&As2[0][kkA][c][arow + u * 64];
                pa[halfA] = f2tf32(aR[u * 4 + c]);
                uint32_t* pb = (uint32_t*)&Bs2[0][kkA][c][arow + u * 64];
                pb[halfA] = f2tf32(bR[u * 4 + c]);
            }
    }
    __syncthreads();

    for (int s = 0; s < numk; s++) {
        const int buf = s & 1;

        // global prefetch of stage s+1
        if (s + 1 < numk) {
            const int k0 = (s + 1) * BK;
#pragma unroll
            for (int u = 0; u < 2; u++) {
                int m = m0 + arow + u * 64;
                const float* ap = A + (size_t)m * K + k0 + akq;
                int n = n0 + arow + u * 64;
                const float* wp = W + (size_t)n * K + k0 + akq;
#pragma unroll
                for (int c = 0; c < 4; c++) {
                    int kk = k0 + akq + c;
                    aR[u * 4 + c] = (kk < K) ? ap[c] : 0.f;
                    bR[u * 4 + c] = (n < N && kk < K) ? wp[c] : 0.f;
                }
            }
        }

        // compute on buf
#pragma unroll
        for (int kk = 0; kk < 2; kk++) {
            uint32_t af[2][4];
#pragma unroll
            for (int mi = 0; mi < 2; mi++) {
                int m = wm * 32 + mi * 16 + gid;
                uint2 U1 = As2[buf][kk][tig][m];
                uint2 U2 = As2[buf][kk][tig][m + 8];
                af[mi][0] = U1.x;
                af[mi][1] = U2.x;
                af[mi][2] = U1.y;
                af[mi][3] = U2.y;
            }
#pragma unroll
            for (int ni = 0; ni < 8; ni++) {
                int n = wn * 64 + ni * 8 + gid;
                uint2 V = Bs2[buf][kk][tig][n];
#pragma unroll
                for (int mi = 0; mi < 2; mi++) {
                    asm volatile(
                        "mma.sync.aligned.m16n8k8.row.col.f32.tf32.tf32.f32 "
                        "{%0,%1,%2,%3},{%4,%5,%6,%7},{%8,%9},{%0,%1,%2,%3};"
                        : "+f"(acc[mi][ni][0]), "+f"(acc[mi][ni][1]),
                          "+f"(acc[mi][ni][2]), "+f"(acc[mi][ni][3])
                        : "r"(af[mi][0]), "r"(af[mi][1]),
                          "r"(af[mi][2]), "r"(af[mi][3]),
                          "r"(V.x), "r"(V.y));
                }
            }
        }

        // STS stage s+1 into the other buffer, then single barrier
        if (s + 1 < numk) {
            const int nb = buf ^ 1;
#pragma unroll
            for (int u = 0; u < 2; u++)
#pragma unroll
                for (int c = 0; c < 4; c++) {
                    uint32_t* pa = (uint32_t*)&As2[nb][kkA][c][arow + u * 64];
                    pa[halfA] = f2tf32(aR[u * 4 + c]);
                    uint32_t* pb = (uint32_t*)&Bs2[nb][kkA][c][arow + u * 64];
                    pb[halfA] = f2tf32(bR[u * 4 + c]);
                }
            __syncthreads();
        }
    }

    // epilogue (unchanged)
#pragma unroll
    for (int mi = 0; mi < 2; mi++) {
#pragma unroll
        for (int ni = 0; ni < 8; ni++) {
            int m = m0 + wm * 32 + mi * 16 + gid;
            int n = n0 + wn * 64 + ni * 8 + tig * 2;
            if (n < N) {
                float bs0 = bi[n] + bh[n];
                float bs1 = bi[n + 1] + bh[n + 1];
                float2 v0 = make_float2(acc[mi][ni][0] + bs0, acc[mi][ni][1] + bs1);
                float2 v1 = make_float2(acc[mi][ni][2] + bs0, acc[mi][ni][3] + bs1);
                *(float2*)&C[(size_t)m * N + n] = v0;
                *(float2*)&C[(size_t)(m + 8) * N + n] = v1;
            }
        }
    }
}

// ---------------------------------------------------------------------------
// Recurrence, quad-gate layout.  FROZEN from round 10 (proven 310 us).
// ---------------------------------------------------------------------------
__device__ __forceinline__ void fence_acqrel_gpu()
{
    asm volatile("fence.acq_rel.gpu;" ::: "memory");
}
__device__ __forceinline__ void red_relaxed_add(int* p)
{
    asm volatile("red.relaxed.gpu.global.add.u32 [%0], 1;" :: "l"(p) : "memory");
}
__device__ __forceinline__ int ld_relaxed(const int* p)
{
    int v;
    asm volatile("ld.relaxed.gpu.global.u32 %0, [%1];" : "=r"(v) : "l"(p) : "memory");
    return v;
}
__device__ __forceinline__ float fast_sigmoid(float x)
{
    return __fdividef(1.f, 1.f + __expf(-x));
}
__device__ __forceinline__ float fast_tanh(float x)
{
    float e = __expf(-2.f * x);
    return (1.f - e) * __fdividef(1.f, 1.f + e);
}

__global__ void __launch_bounds__(224, 1)
recur_kernel(const float* __restrict__ Whh,   // [2][800][200]
             int layer_sel)
{
    const int r    = (int)(blockIdx.x & 3);   // rank in group 0..3
    const int pair = (int)(blockIdx.x >> 2);  // 0..31
    const int dir  = pair >> 4;
    const int b    = pair & 15;
    const int tid  = threadIdx.x;
    const int len  = g_lens[b];
    const int tbase = layer_sel ? 512 : 0;
    int* cnt = &g_bar[pair * 64];
    float* outh = layer_sel ? g_h1 : g_h0;

    __shared__ float4 hs4[50];
    float* hs = (float*)hs4;

    const int q       = tid & 3;
    const int u_local = tid >> 2;
    const int gu      = r * 50 + u_local;
    const int grow    = q * 200 + gu;
    const unsigned shmask = (tid < 192) ? 0xFFFFFFFFu : 0xFFu;
    const int lbase = (tid & 31) & ~3;

    float4 W4[50];
    if (tid < 200) {
        const float4* wp = (const float4*)(Whh + ((size_t)dir * G4 + grow) * HID);
#pragma unroll
        for (int kk = 0; kk < 50; kk++) W4[kk] = wp[kk];
    }
    if (tid < 50) hs4[tid] = make_float4(0.f, 0.f, 0.f, 0.f);

    float c = 0.f;
    const long gstep = dir ? -(long)G4 : (long)G4;
    const int  tpf   = dir ? (SEQL - 1) : 0;
    const float* gp  = g_gx + ((size_t)dir * BATCH + b) * SEQL * G4
                            + (size_t)tpf * G4 + grow;
    float gcur = 0.f;
    if (tid < 200) gcur = __ldcg(gp);
    __syncthreads();

    for (int t = 0; t < SEQL; t++) {
        const int tp  = dir ? (SEQL - 1 - t) : t;
        const int par = t & 1;
        const float mt = (tp < len) ? 1.f : 0.f;

        if (tid < 200) {
            float a0 = 0.f, a1 = 0.f, a2 = 0.f, a3 = 0.f;
#pragma unroll
            for (int kk = 0; kk < 50; kk++) {
                float4 hv = hs4[kk];
                a0 += W4[kk].x * hv.x;
                a1 += W4[kk].y * hv.y;
                a2 += W4[kk].z * hv.z;
                a3 += W4[kk].w * hv.w;
            }
            float s = (a0 + a1) + (a2 + a3) + gcur;
            gp += gstep;
            if (t + 1 < SEQL) gcur = __ldcg(gp);

            float v = (q == 2) ? fast_tanh(s) : fast_sigmoid(s);
            float ii = __shfl_sync(shmask, v, lbase + 0);
            float ff = __shfl_sync(shmask, v, lbase + 1);
            float gg = __shfl_sync(shmask, v, lbase + 2);
            float oo = __shfl_sync(shmask, v, lbase + 3);

            float cn = ff * c + ii * gg;
            float hn = oo * fast_tanh(cn);
            float hp = hs[gu];
            float hnew = mt * hn + (1.f - mt) * hp;
            c = mt * cn + (1.f - mt) * c;

            if (q == 0) {
                outh[((size_t)b * SEQL + tp) * LSTMD + dir * HID + gu] = mt * hn;
                __stcg(g_hx + ((size_t)par * 32 + pair) * 208 + gu, hnew);
            }
        }
        __syncthreads();

        if (tid == 0) {
            fence_acqrel_gpu();
            red_relaxed_add(cnt);
            const int target = tbase + 4 * (t + 1);
            while (ld_relaxed(cnt) < target) { }
            fence_acqrel_gpu();
        }
        __syncthreads();

        if (tid < 200)
            hs[tid] = __ldcg(g_hx + ((size_t)par * 32 + pair) * 208 + tid);
        __syncthreads();
    }
}

// ---------------------------------------------------------------------------
// s -> (i,j) table + lens-2 tail
// ---------------------------------------------------------------------------
__global__ void ij_kernel(float* __restrict__ out, int extra)
{
    int idx = blockIdx.x * blockDim.x + threadIdx.x;
    if (idx < extra && idx < BATCH)
        out[(size_t)OUT_BASE + idx] = (float)(g_lens[idx] - 2);
    if (idx >= BATCH * SMAX) return;
    int s = idx % SMAX;
    int b = idx / SMAX;
    int n = g_lens[b] - 1;
    int cnt = n * (n - 1) / 2;
    int val = 0;
    if (s < cnt) {
        float fn = (float)(2 * n - 1);
        int i = (int)floorf((fn - sqrtf(fn * fn - 8.0f * (float)s)) * 0.5f);
        if (i < 0) i = 0;
        if (i > n - 2) i = n - 2;
        while ((i + 1) * (2 * n - 2 - i) / 2 <= s) i++;
        while (i > 0 && i * (2 * n - 1 - i) / 2 > s) i--;
        int j = i + 1 + (s - i * (2 * n - 1 - i) / 2);
        val = (i << 8) | j;
    }
    g_ij[idx] = val;
}

// ---------------------------------------------------------------------------
// Span emit (float4 granularity)
// ---------------------------------------------------------------------------
__global__ void span_kernel(float* __restrict__ out)
{
    long idx = (long)blockIdx.x * blockDim.x + threadIdx.x; // over 16*8001*100
    if (idx >= (long)BATCH * SMAX * 100) return;
    int d4 = (int)(idx % 100);
    int bs = (int)(idx / 100);
    int s = bs % SMAX;
    int b = bs / SMAX;
    int n = g_lens[b] - 1;
    int cnt = n * (n - 1) / 2;
    float4 v = make_float4(0.f, 0.f, 0.f, 0.f);
    if (s < cnt) {
        int p = g_ij[bs];
        int i = p >> 8;
        int j = p & 255;
        const float4* hb = (const float4*)(g_h1 + (size_t)b * SEQL * LSTMD);
        float4 x, y;
        if (d4 < 50) {
            x = hb[j * 100 + d4];
            y = hb[i * 100 + d4];
        } else {
            x = hb[(i + 1) * 100 + d4];
            y = hb[(j + 1) * 100 + d4];
        }
        v.x = x.x - y.x; v.y = x.y - y.y; v.z = x.z - y.z; v.w = x.w - y.w;
    }
    ((float4*)out)[idx] = v;
}

// ---------------------------------------------------------------------------
// Launch.  ncu captures launch index 3 -> gemm0 there.
//   0 lens, 1 embed_bert, 2 embed_wordmisc, 3 gemm0, 4 recur0,
//   5 gemm1, 6 recur1, 7 ij, 8 span
// ---------------------------------------------------------------------------
extern "C" void kernel_launch(void* const* d_in, const int* in_sizes, int n_in,
                              void* d_out, int out_size)
{
    const float* ext_emb  = (const float*)d_in[0];
    const float* word_emb = (const float*)d_in[1];
    const float* pos_emb  = (const float*)d_in[2];
    const float* dep_emb  = (const float*)d_in[3];
    const float* ent_emb  = (const float*)d_in[4];
    const float* iob_emb  = (const float*)d_in[5];
    const float* w_ih_l0  = (const float*)d_in[6];
    const float* w_hh_l0  = (const float*)d_in[7];
    const float* b_ih_l0  = (const float*)d_in[8];
    const float* b_hh_l0  = (const float*)d_in[9];
    const float* w_ih_l1  = (const float*)d_in[10];
    const float* w_hh_l1  = (const float*)d_in[11];
    const float* b_ih_l1  = (const float*)d_in[12];
    const float* b_hh_l1  = (const float*)d_in[13];
    const float* bert     = (const float*)d_in[14];
    const int* word_idxs  = (const int*)d_in[15];
    const int* pos_idxs   = (const int*)d_in[16];
    const int* dep_idxs   = (const int*)d_in[17];
    const int* ent_idxs   = (const int*)d_in[18];
    const int* iob_idxs   = (const int*)d_in[19];
    float* out = (float*)d_out;

    // 0. lengths + padded counter reset
    lens_kernel<<<BATCH, SEQL>>>(word_idxs);

    // 1. embed: bert slice
    {
        long tb = (long)ML * 768;
        embed_bert_kernel<<<(int)((tb + 255) / 256), 256>>>(bert);
    }

    // 2. embed: word + misc slices
    {
        long tw = (long)ML * 450;
        embed_wordmisc_kernel<<<(int)((tw + 255) / 256), 256>>>(
            ext_emb, word_emb, pos_emb, dep_emb, ent_emb, iob_emb,
            word_idxs, pos_idxs, dep_idxs, ent_idxs, iob_idxs);
    }

    // 3. layer0 input projection  (M=2048, N=800, K=1218), A = g_emb
    {
        dim3 grid((G4 + BN - 1) / BN, ML / BM, 2);
        gemm_tf32_kernel<<<grid, 256>>>(w_ih_l0, b_ih_l0, b_hh_l0,
                                        ML, G4, IN_DIM, 0);
    }

    // 4. layer0 recurrence (128 CTAs, 32 groups x 4)
    recur_kernel<<<128, 224>>>(w_hh_l0, 0);

    // 5. layer1 input projection (M=2048, N=800, K=400), A = g_h0
    {
        dim3 grid((G4 + BN - 1) / BN, ML / BM, 2);
        gemm_tf32_kernel<<<grid, 256>>>(w_ih_l1, b_ih_l1, b_hh_l1,
                                        ML, G4, LSTMD, 1);
    }

    // 6. layer1 recurrence
    recur_kernel<<<128, 224>>>(w_hh_l1, 1);

    // 7. s -> (i,j) table (+ lens-2 tail if present)
    {
        int extra = out_size - OUT_BASE;
        if (extra < 0) extra = 0;
        int tot = BATCH * SMAX;
        ij_kernel<<<(tot + 255) / 256, 256>>>(out, extra);
    }

    // 8. span emit
    {
        long tot = (long)BATCH * SMAX * 100;
        int blocks = (int)((tot + 255) / 256);
        span_kernel<<<blocks, 256>>>(out);
    }
}